// round 15
// baseline (speedup 1.0000x reference)
#include <cuda_runtime.h>

#define DD 64
#define HH 128
#define WW 128
#define NVOX (DD*HH*WW)

// padded layout (zero borders, zero-initialized statics)
#define PH 132
#define PW 136
#define PPLANE (PH*PW)
#define PSZ (68*PPLANE)

// ---- static device state ----
// (I', s): I' = I * sqrt(2*log2(e)) pre-scaled; s = dB1m*q + dB0*m.
// padding stays (0,0) forever = mask 0.
__device__ float2 g_pA[PSZ];
__device__ float2 g_pB[PSZ];
__device__ float  g_duS2[NVOX];  // du - (dA0 - rB*dB0)*S
__device__ float  g_coef[4];     // rB, dB0, dB1m, -

// ---- blur taps (sigma=1, radius 2, normalized) ----
constexpr double c_E05 = 0.60653065971263342426;
constexpr double c_E2  = 0.13533528323661269189;
constexpr double c_KS  = 1.0 + 2.0*c_E05 + 2.0*c_E2;
#define K0F ((float)(1.0   / c_KS))
#define K1F ((float)(c_E05 / c_KS))
#define K2F ((float)(c_E2  / c_KS))

// bilateral with pre-scaled I': w = 2^(lsc - df'^2)
#define SQEXP (1.6986436f)             // sqrt(2*log2(e))
#define LSC1  (-0.3205988979944306f)
#define LSC2  (-0.6411977959888612f)
#define LSC3  (-0.9617966939832918f)

#define LOG_SQRT_2PI 0.91893853320467274178f

__device__ __forceinline__ float ex2f(float x) {
    float r; asm("ex2.approx.ftz.f32 %0, %1;" : "=f"(r) : "f"(x)); return r;
}
__device__ __forceinline__ float sigmoidf_fast(float x) {
    return __fdividef(1.0f, 1.0f + ex2f(-1.4426950408889634f * x));
}
__device__ __forceinline__ float axis_sum(int i, int N) {
    float m = 1.f;
    if (i == 0) m -= (K1F + K2F); else if (i == 1) m -= K2F;
    int j = N - 1 - i;
    if (j == 0) m -= (K1F + K2F); else if (j == 1) m -= K2F;
    return m;
}

__global__ void init_kernel(const float* __restrict__ img,
                            const float* __restrict__ h,
                            const float* __restrict__ f1,
                            const float* __restrict__ w0,
                            const float* __restrict__ sw,
                            const float* __restrict__ bw,
                            const float* __restrict__ cm) {
    int i = blockIdx.x * blockDim.x + threadIdx.x;
    if (i >= NVOX) return;
    float cm0 = cm[2] - cm[0];
    float cm1 = cm[3] - cm[1];
    float dA0  = cm0 * sw[0] + cm1 * sw[2];
    float dA1  = cm0 * sw[1] + cm1 * sw[3];
    float dB0  = cm0 * bw[0] + cm1 * bw[2];
    float dB1  = cm0 * bw[1] + cm1 * bw[3];
    float dA1m = dA1 - dA0;
    float dB1m = dB1 - dB0;
    float rB   = dA1m / dB1m;
    if (i == 0) {
        g_coef[0] = rB; g_coef[1] = dB0; g_coef[2] = dB1m;
    }
    int x = i & 127;
    int y = (i >> 7) & 127;
    int z = i >> 14;

    float I  = img[i];
    float d  = h[i + NVOX] - h[i];
    float du = d * (f1[i] - w0[0] + 0.5f*I*I + LOG_SQRT_2PI);
    float S  = axis_sum(z, DD) * axis_sum(y, HH) * axis_sum(x, WW);
    g_duS2[i] = du - (dA0 - rB * dB0) * S;

    float q = sigmoidf_fast(d);
    float s = fmaf(dB1m, q, dB0);
    int p = ((z + 2)*PH + (y + 2))*PW + (x + 4);
    g_pA[p] = make_float2(I * SQEXP, s);
}

// smem geometry (tile 32x8x8, halo z/y=2, x=2):
//   region A [0, 5184)f     : sS f32 [12 z][12 y][36 x] -> later t2 f32 [12][8][32] (3072f)
//   region B [5184, 9792)f  : sI f32 [10 zp][10 yr][34 x] (3400f) -> later t1 f32 [12][12][32] (4608f)
#define SSROW 36
#define SSPL  (12*36)   // 432
#define SIROW 34
#define SIPL  (10*34)   // 340
#define POOLF (5184 + 4608)   // 9792 floats = 39168 B

// R11-proven 2x2 (z,y) quad bilateral: 48 positions serve 104 taps.
__device__ __forceinline__ void bilat_quad(
    const float* __restrict__ sI, const float* __restrict__ sS,
    int vzb, int wyb, int lane, float Icq[2][2], float pbq[2][2])
{
    float den[2][2], acc[2][2];
    #pragma unroll
    for (int zi = 0; zi < 2; zi++)
        #pragma unroll
        for (int yi = 0; yi < 2; yi++) {
            Icq[zi][yi] = sI[(vzb+1+zi)*SIPL + (wyb+1+yi)*SIROW + lane + 1];
            acc[zi][yi] = sS[(vzb+2+zi)*SSPL + (wyb+2+yi)*SSROW + lane + 2];
            den[zi][yi] = 1.f;        // center weight = 1 exactly
        }
    #pragma unroll
    for (int pp = 0; pp < 4; pp++) {
        #pragma unroll
        for (int rr = 0; rr < 4; rr++) {
            #pragma unroll
            for (int cc = 0; cc < 3; cc++) {
                float Iv = sI[(vzb+pp)*SIPL + (wyb+rr)*SIROW + lane + cc];
                float Sv = sS[(vzb+1+pp)*SSPL + (wyb+1+rr)*SSROW + lane + 1 + cc];
                #pragma unroll
                for (int zi = 0; zi < 2; zi++) {
                    const int dz = pp - 1 - zi;
                    if (dz < -1 || dz > 1) continue;
                    #pragma unroll
                    for (int yi = 0; yi < 2; yi++) {
                        const int dy = rr - 1 - yi;
                        if (dy < -1 || dy > 1) continue;
                        const int d2 = dz*dz + dy*dy + (cc-1)*(cc-1);
                        if (d2 == 0) continue;
                        const float lsc = (d2 == 1) ? LSC1 : (d2 == 2) ? LSC2 : LSC3;
                        float df = Icq[zi][yi] - Iv;
                        float w  = ex2f(fmaf(df, -df, lsc));
                        den[zi][yi] += w;
                        acc[zi][yi] = fmaf(w, Sv, acc[zi][yi]);
                    }
                }
            }
        }
    }
    #pragma unroll
    for (int zi = 0; zi < 2; zi++)
        #pragma unroll
        for (int yi = 0; yi < 2; yi++)
            pbq[zi][yi] = __fdividef(acc[zi][yi], den[zi][yi]);
}

template<int LAST>
__global__ void __launch_bounds__(256, 4)
iter_kernel(int flip, float* __restrict__ out,
            const float* __restrict__ f1, int copyf1)
{
    __shared__ __align__(16) float pool[POOLF];
    float* sS = pool;            // [12][12][36]
    float* t2 = pool;            // [12][8][32], aliases dead sS after x-blur
    float* sI = pool + 5184;     // [10][10][34]
    float* t1 = pool + 5184;     // [12][12][32], aliases dead sI after bilateral

    const float2* __restrict__ qprev = flip ? g_pB : g_pA;
    float2*       __restrict__ qnext = flip ? g_pA : g_pB;

    const int lane = threadIdx.x;                 // 0..31 (x)
    const int ty   = threadIdx.y;                 // 0..1
    const int tz   = threadIdx.z;                 // 0..3
    const int tid  = lane + 32*(ty + 2*tz);
    const int wid  = ty + 2*tz;                   // warp 0..7
    const int x0 = blockIdx.x << 5;
    const int y0 = blockIdx.y << 3;
    const int z0 = blockIdx.z << 3;
    const int wy = ty << 1;                       // base y of first quad (0 or 2)
    const int vz = tz << 1;                       // base z of pair (0,2,4,6)

    // padded index of (z0-2, y0-2, x0-2)
    const int pbase = (z0*PH + y0)*PW + x0 + 2;

    // ---- halo load: 144 rows (12z x 12y) of 36, 18 per warp (balanced) ----
    #pragma unroll
    for (int j = 0; j < 18; j++) {
        int e  = wid + (j << 3);      // 0..143
        int lz = e / 12;
        int ly = e - lz*12;
        int a  = pbase + lz*PPLANE + ly*PW + lane;
        float2 v = qprev[a];
        sS[lz*SSPL + ly*SSROW + lane] = v.y;
        float2 v2 = make_float2(0.f, 0.f);
        if (lane < 4) {
            v2 = qprev[a + 32];
            sS[lz*SSPL + ly*SSROW + lane + 32] = v2.y;
        }
        bool io = (unsigned)(lz - 1) < 10u && (unsigned)(ly - 1) < 10u;
        if (io) {
            int sb = (lz-1)*SIPL + (ly-1)*SIROW;
            if (lane >= 1) sI[sb + lane - 1]  = v.x;
            if (lane < 3)  sI[sb + lane + 31] = v2.x;
        }
    }
    __syncthreads();

    // ---- bilateral: two sequential 2x2 quads (y groups wy and wy+4) ----
    float Ic[2][2][2], pb[2][2][2];
    bilat_quad(sI, sS, vz, wy,     lane, Ic[0], pb[0]);
    bilat_quad(sI, sS, vz, wy + 4, lane, Ic[1], pb[1]);
    __syncthreads();   // all sI reads done; t1 may overwrite

    // ---- x-blur sS -> t1 [12][12][32]: 1152 quads (4x256 + 128) ----
    #pragma unroll
    for (int k = 0; k < 5; k++) {
        int e = tid + (k << 8);
        if (k == 4 && tid >= 128) break;
        int row = e >> 3;             // 0..143
        int qx  = e & 7;
        const float* rp = sS + row*SSROW + (qx << 2);
        float4 a = *(const float4*)rp;
        float4 b = *(const float4*)(rp + 4);
        float4 o;
        o.x = K2F*(a.x + b.x) + K1F*(a.y + a.w) + K0F*a.z;
        o.y = K2F*(a.y + b.y) + K1F*(a.z + b.x) + K0F*a.w;
        o.z = K2F*(a.z + b.z) + K1F*(a.w + b.y) + K0F*b.x;
        o.w = K2F*(a.w + b.w) + K1F*(b.x + b.z) + K0F*b.y;
        *(float4*)(t1 + row*32 + (qx << 2)) = o;
    }
    __syncthreads();   // all sS reads done; t2 may overwrite

    // ---- y-blur t1 -> t2 [12][8][32]: 768 quads, 3 per thread ----
    #pragma unroll
    for (int k = 0; k < 3; k++) {
        int e  = tid + (k << 8);
        int lz = e >> 6;
        int ry = (e >> 3) & 7;
        int qx = e & 7;
        const float* bp = t1 + (lz*12 + ry)*32 + (qx << 2);
        float4 r0 = *(const float4*)(bp);
        float4 r1 = *(const float4*)(bp + 32);
        float4 r2 = *(const float4*)(bp + 64);
        float4 r3 = *(const float4*)(bp + 96);
        float4 r4 = *(const float4*)(bp + 128);
        float4 o;
        o.x = K2F*(r0.x+r4.x) + K1F*(r1.x+r3.x) + K0F*r2.x;
        o.y = K2F*(r0.y+r4.y) + K1F*(r1.y+r3.y) + K0F*r2.y;
        o.z = K2F*(r0.z+r4.z) + K1F*(r1.z+r3.z) + K0F*r2.z;
        o.w = K2F*(r0.w+r4.w) + K1F*(r1.w+r3.w) + K0F*r2.w;
        *(float4*)(t2 + (lz*8 + ry)*32 + (qx << 2)) = o;
    }
    __syncthreads();

    // ---- z-blur + combine + write (8 voxels) ----
    const float rB   = g_coef[0];
    const float dB0  = g_coef[1];
    const float dB1m = g_coef[2];

    #pragma unroll
    for (int g = 0; g < 2; g++) {
        const int wyb = wy + (g << 2);
        #pragma unroll
        for (int yi = 0; yi < 2; yi++) {
            const int yr = wyb + yi;
            float c0 = t2[((vz+0)*8 + yr)*32 + lane];
            float c1 = t2[((vz+1)*8 + yr)*32 + lane];
            float c2 = t2[((vz+2)*8 + yr)*32 + lane];
            float c3 = t2[((vz+3)*8 + yr)*32 + lane];
            float c4 = t2[((vz+4)*8 + yr)*32 + lane];
            float c5 = t2[((vz+5)*8 + yr)*32 + lane];
            float sp0 = K2F*(c0+c4) + K1F*(c1+c3) + K0F*c2;
            float sp1 = K2F*(c1+c5) + K1F*(c2+c4) + K0F*c3;

            const int gy = y0 + yr;
            const int gz = z0 + vz;
            const int gi0 = (gz*HH + gy)*WW + x0 + lane;
            const int gi1 = gi0 + HH*WW;

            float d0 = g_duS2[gi0] - rB*sp0 - pb[g][0][yi];
            float d1 = g_duS2[gi1] - rB*sp1 - pb[g][1][yi];
            float res0 = sigmoidf_fast(d0);
            float res1 = sigmoidf_fast(d1);

            if (LAST) {
                out[gi0]        = 1.f - res0;
                out[NVOX + gi0] = res0;
                out[gi1]        = 1.f - res1;
                out[NVOX + gi1] = res1;
                if (copyf1) {
                    out[2*NVOX + gi0] = f1[gi0];
                    out[2*NVOX + gi1] = f1[gi1];
                }
            } else {
                int pc = pbase + (vz+2)*PPLANE + (yr+2)*PW + lane + 2;
                qnext[pc]          = make_float2(Ic[g][0][yi], fmaf(dB1m, res0, dB0));
                qnext[pc + PPLANE] = make_float2(Ic[g][1][yi], fmaf(dB1m, res1, dB0));
            }
        }
    }
}

extern "C" void kernel_launch(void* const* d_in, const int* in_sizes, int n_in,
                              void* d_out, int out_size) {
    const float* img = (const float*)d_in[0];
    const float* h   = (const float*)d_in[1];
    const float* f1  = (const float*)d_in[2];
    const float* w0  = (const float*)d_in[3];
    const float* sw  = (const float*)d_in[4];
    const float* bw  = (const float*)d_in[5];
    const float* cm  = (const float*)d_in[6];
    float* out = (float*)d_out;

    cudaFuncSetAttribute(iter_kernel<0>,
                         cudaFuncAttributePreferredSharedMemoryCarveout, 100);
    cudaFuncSetAttribute(iter_kernel<1>,
                         cudaFuncAttributePreferredSharedMemoryCarveout, 100);

    init_kernel<<<NVOX/256, 256>>>(img, h, f1, w0, sw, bw, cm);

    dim3 blk(32, 2, 4);
    dim3 grd(WW/32, HH/8, DD/8);   // 4 x 16 x 8 = 512 blocks (one wave at 4/SM)
    int copyf1 = (out_size >= 3 * NVOX) ? 1 : 0;
    iter_kernel<0><<<grd, blk>>>(0, out, f1, copyf1);   // A -> B
    iter_kernel<0><<<grd, blk>>>(1, out, f1, copyf1);   // B -> A
    iter_kernel<0><<<grd, blk>>>(0, out, f1, copyf1);   // A -> B
    iter_kernel<0><<<grd, blk>>>(1, out, f1, copyf1);   // B -> A
    iter_kernel<1><<<grd, blk>>>(0, out, f1, copyf1);   // A -> out
}

// round 16
// speedup vs baseline: 1.2629x; 1.2629x over previous
#include <cuda_runtime.h>

#define DD 64
#define HH 128
#define WW 128
#define NVOX (DD*HH*WW)

// padded layout (zero borders, zero-initialized statics)
#define PH 132
#define PW 136
#define PPLANE (PH*PW)
#define PSZ (68*PPLANE)

// ---- static device state ----
// (I', s): I' = I * sqrt(2*log2(e)) pre-scaled; s = dB1m*q + dB0*m.
// padding stays (0,0) forever = mask 0.
__device__ float2 g_pA[PSZ];
__device__ float2 g_pB[PSZ];
__device__ float  g_duS2[NVOX];  // du - (dA0 - rB*dB0)*S
__device__ float  g_coef[4];     // rB, dB0, dB1m, -

// ---- blur taps (sigma=1, radius 2, normalized) ----
constexpr double c_E05 = 0.60653065971263342426;
constexpr double c_E2  = 0.13533528323661269189;
constexpr double c_KS  = 1.0 + 2.0*c_E05 + 2.0*c_E2;
#define K0F ((float)(1.0   / c_KS))
#define K1F ((float)(c_E05 / c_KS))
#define K2F ((float)(c_E2  / c_KS))

// bilateral with pre-scaled I': w = 2^(lsc - df'^2), df' = Ic' - Iv'
#define SQEXP (1.6986436f)             // sqrt(2*log2(e))
#define LSC1  (-0.3205988979944306f)
#define LSC2  (-0.6411977959888612f)
#define LSC3  (-0.9617966939832918f)

#define LOG_SQRT_2PI 0.91893853320467274178f

__device__ __forceinline__ float ex2f(float x) {
    float r; asm("ex2.approx.ftz.f32 %0, %1;" : "=f"(r) : "f"(x)); return r;
}
__device__ __forceinline__ float sigmoidf_fast(float x) {
    return __fdividef(1.0f, 1.0f + ex2f(-1.4426950408889634f * x));
}
__device__ __forceinline__ float axis_sum(int i, int N) {
    float m = 1.f;
    if (i == 0) m -= (K1F + K2F); else if (i == 1) m -= K2F;
    int j = N - 1 - i;
    if (j == 0) m -= (K1F + K2F); else if (j == 1) m -= K2F;
    return m;
}

__global__ void init_kernel(const float* __restrict__ img,
                            const float* __restrict__ h,
                            const float* __restrict__ f1,
                            const float* __restrict__ w0,
                            const float* __restrict__ sw,
                            const float* __restrict__ bw,
                            const float* __restrict__ cm) {
    int i = blockIdx.x * blockDim.x + threadIdx.x;
    if (i >= NVOX) return;
    float cm0 = cm[2] - cm[0];
    float cm1 = cm[3] - cm[1];
    float dA0  = cm0 * sw[0] + cm1 * sw[2];
    float dA1  = cm0 * sw[1] + cm1 * sw[3];
    float dB0  = cm0 * bw[0] + cm1 * bw[2];
    float dB1  = cm0 * bw[1] + cm1 * bw[3];
    float dA1m = dA1 - dA0;
    float dB1m = dB1 - dB0;
    float rB   = dA1m / dB1m;
    if (i == 0) {
        g_coef[0] = rB; g_coef[1] = dB0; g_coef[2] = dB1m;
    }
    int x = i & 127;
    int y = (i >> 7) & 127;
    int z = i >> 14;

    float I  = img[i];
    float d  = h[i + NVOX] - h[i];
    float du = d * (f1[i] - w0[0] + 0.5f*I*I + LOG_SQRT_2PI);
    float S  = axis_sum(z, DD) * axis_sum(y, HH) * axis_sum(x, WW);
    g_duS2[i] = du - (dA0 - rB * dB0) * S;

    float q = sigmoidf_fast(d);
    float s = fmaf(dB1m, q, dB0);
    int p = ((z + 2)*PH + (y + 2))*PW + (x + 4);
    g_pA[p] = make_float2(I * SQEXP, s);
}

// smem geometry (dynamic pool, 27648 B):
//   sI [12 z][8 y][36 x] f32 (3456f); later aliased by t1 [12][8][32] (3072f)
//   sS [12 z][8 y][36 x] f32 (3456f); later aliased by t2 [12][4][32] (1536f)
#define SROW 36
#define SPL  (8*36)     // z-plane stride
#define POOLF (2*3456)  // 6912 floats = 27648 bytes

template<int LAST>
__global__ void __launch_bounds__(256)
iter_kernel(int flip, float* __restrict__ out,
            const float* __restrict__ f1, int copyf1)
{
    extern __shared__ __align__(16) float pool[];
    float* sI = pool;            // [12][8][36]; later aliased by t1 [12][8][32]
    float* sS = pool + 3456;     // [12][8][36]; later aliased by t2 [12][4][32]
    float* t1 = pool;
    float* t2 = pool + 3456;

    const float2* __restrict__ qprev = flip ? g_pB : g_pA;
    float2*       __restrict__ qnext = flip ? g_pA : g_pB;

    const int lane = threadIdx.x;                 // 0..31 (x)
    const int ty   = threadIdx.y;                 // 0..1  (y pair)
    const int tz   = threadIdx.z;                 // 0..3  (z pair)
    const int tid  = lane + 32*(ty + 2*tz);
    const int wid  = ty + 2*tz;                   // warp 0..7
    const int x0 = blockIdx.x << 5;
    const int y0 = blockIdx.y << 2;
    const int z0 = blockIdx.z << 3;
    const int wy = ty << 1;                       // tile y base of pair
    const int vz = tz << 1;                       // tile z base of pair

    // padded index of (z0-2, y0-2, x0-2)
    const int pbase = (z0*PH + y0)*PW + x0 + 2;

    // ---- halo load: 96 rows (12z x 8y) x 36, split into scalar planes ----
    #pragma unroll
    for (int k = 0; k < 12; k++) {
        int r  = wid + (k << 3);      // 0..95
        int lz = r >> 3;
        int ly = r & 7;
        int a  = pbase + lz*PPLANE + ly*PW + lane;
        int si = lz*SPL + ly*SROW + lane;
        float2 v = qprev[a];
        sI[si] = v.x;
        sS[si] = v.y;
        if (lane < 4) {
            float2 v2 = qprev[a + 32];
            sI[si + 32] = v2.x;
            sS[si + 32] = v2.y;
        }
    }
    __syncthreads();

    // ---- bilateral 2x2 quad: 48 shared positions serve 104 taps ----
    float Ic[2][2], den[2][2], acc[2][2], pb[2][2];
    #pragma unroll
    for (int zi = 0; zi < 2; zi++)
        #pragma unroll
        for (int yi = 0; yi < 2; yi++) {
            int c = (vz+2+zi)*SPL + (wy+2+yi)*SROW + lane + 2;
            Ic[zi][yi]  = sI[c];
            acc[zi][yi] = sS[c];      // center weight = 1 exactly
            den[zi][yi] = 1.f;
        }
    #pragma unroll
    for (int pp = 0; pp < 4; pp++) {
        #pragma unroll
        for (int rr = 0; rr < 4; rr++) {
            #pragma unroll
            for (int cc = 0; cc < 3; cc++) {
                const int idx = (vz+1+pp)*SPL + (wy+1+rr)*SROW + lane + 1 + cc;
                float Iv = sI[idx];
                float Sv = sS[idx];
                #pragma unroll
                for (int zi = 0; zi < 2; zi++) {
                    const int dz = pp - 1 - zi;
                    if (dz < -1 || dz > 1) continue;
                    #pragma unroll
                    for (int yi = 0; yi < 2; yi++) {
                        const int dy = rr - 1 - yi;
                        if (dy < -1 || dy > 1) continue;
                        const int d2 = dz*dz + dy*dy + (cc-1)*(cc-1);
                        if (d2 == 0) continue;
                        const float lsc = (d2 == 1) ? LSC1 : (d2 == 2) ? LSC2 : LSC3;
                        float df = Ic[zi][yi] - Iv;
                        float w  = ex2f(fmaf(df, -df, lsc));
                        den[zi][yi] += w;
                        acc[zi][yi] = fmaf(w, Sv, acc[zi][yi]);
                    }
                }
            }
        }
    }
    #pragma unroll
    for (int zi = 0; zi < 2; zi++)
        #pragma unroll
        for (int yi = 0; yi < 2; yi++)
            pb[zi][yi] = __fdividef(acc[zi][yi], den[zi][yi]);
    __syncthreads();   // all sI reads done; t1 may overwrite

    // ---- x-blur on sS -> t1 [12][8][32]: 768 quads, 3 per thread ----
    #pragma unroll
    for (int k = 0; k < 3; k++) {
        int e   = tid + (k << 8);
        int row = e >> 3;             // 0..95
        int qx  = e & 7;
        const float* rp = sS + row*SROW + (qx << 2);
        float4 a = *(const float4*)rp;        // s[j .. j+3]
        float4 b = *(const float4*)(rp + 4);  // s[j+4 .. j+7]
        float4 o;
        o.x = K2F*(a.x + b.x) + K1F*(a.y + a.w) + K0F*a.z;
        o.y = K2F*(a.y + b.y) + K1F*(a.z + b.x) + K0F*a.w;
        o.z = K2F*(a.z + b.z) + K1F*(a.w + b.y) + K0F*b.x;
        o.w = K2F*(a.w + b.w) + K1F*(b.x + b.z) + K0F*b.y;
        *(float4*)(t1 + row*32 + (qx << 2)) = o;
    }
    __syncthreads();   // all sS reads done; t2 may overwrite

    // ---- y-blur t1 -> t2 [12][4][32]: 384 quads (256 + 128) ----
    {
        int r2 = tid >> 3;            // 0..31
        int q2 = tid & 7;
        int lz = r2 >> 2;
        int yy = r2 & 3;
        const float* bp = t1 + (lz*8 + yy)*32 + (q2 << 2);
        float4 r0 = *(const float4*)(bp);
        float4 r1 = *(const float4*)(bp + 32);
        float4 r2v = *(const float4*)(bp + 64);
        float4 r3 = *(const float4*)(bp + 96);
        float4 r4 = *(const float4*)(bp + 128);
        float4 o;
        o.x = K2F*(r0.x+r4.x) + K1F*(r1.x+r3.x) + K0F*r2v.x;
        o.y = K2F*(r0.y+r4.y) + K1F*(r1.y+r3.y) + K0F*r2v.y;
        o.z = K2F*(r0.z+r4.z) + K1F*(r1.z+r3.z) + K0F*r2v.z;
        o.w = K2F*(r0.w+r4.w) + K1F*(r1.w+r3.w) + K0F*r2v.w;
        *(float4*)(t2 + (lz*4 + yy)*32 + (q2 << 2)) = o;
    }
    if (tid < 128) {
        int e2 = tid + 256;
        int r2 = e2 >> 3;             // 32..47
        int q2 = e2 & 7;
        int lz = r2 >> 2;
        int yy = r2 & 3;
        const float* bp = t1 + (lz*8 + yy)*32 + (q2 << 2);
        float4 r0 = *(const float4*)(bp);
        float4 r1 = *(const float4*)(bp + 32);
        float4 r2v = *(const float4*)(bp + 64);
        float4 r3 = *(const float4*)(bp + 96);
        float4 r4 = *(const float4*)(bp + 128);
        float4 o;
        o.x = K2F*(r0.x+r4.x) + K1F*(r1.x+r3.x) + K0F*r2v.x;
        o.y = K2F*(r0.y+r4.y) + K1F*(r1.y+r3.y) + K0F*r2v.y;
        o.z = K2F*(r0.z+r4.z) + K1F*(r1.z+r3.z) + K0F*r2v.z;
        o.w = K2F*(r0.w+r4.w) + K1F*(r1.w+r3.w) + K0F*r2v.w;
        *(float4*)(t2 + (lz*4 + yy)*32 + (q2 << 2)) = o;
    }
    __syncthreads();

    // ---- z-blur + combine + write (4 voxels) ----
    const float rB   = g_coef[0];
    const float dB0  = g_coef[1];
    const float dB1m = g_coef[2];

    #pragma unroll
    for (int yi = 0; yi < 2; yi++) {
        float c0 = t2[((vz+0)*4 + wy+yi)*32 + lane];
        float c1 = t2[((vz+1)*4 + wy+yi)*32 + lane];
        float c2 = t2[((vz+2)*4 + wy+yi)*32 + lane];
        float c3 = t2[((vz+3)*4 + wy+yi)*32 + lane];
        float c4 = t2[((vz+4)*4 + wy+yi)*32 + lane];
        float c5 = t2[((vz+5)*4 + wy+yi)*32 + lane];
        float sp0 = K2F*(c0+c4) + K1F*(c1+c3) + K0F*c2;
        float sp1 = K2F*(c1+c5) + K1F*(c2+c4) + K0F*c3;

        const int gy = y0 + wy + yi;
        const int gz = z0 + vz;
        const int gi0 = (gz*HH + gy)*WW + x0 + lane;
        const int gi1 = gi0 + HH*WW;

        float d0 = g_duS2[gi0] - rB*sp0 - pb[0][yi];
        float d1 = g_duS2[gi1] - rB*sp1 - pb[1][yi];
        float res0 = sigmoidf_fast(d0);
        float res1 = sigmoidf_fast(d1);

        if (LAST) {
            out[gi0]        = 1.f - res0;
            out[NVOX + gi0] = res0;
            out[gi1]        = 1.f - res1;
            out[NVOX + gi1] = res1;
            if (copyf1) {
                out[2*NVOX + gi0] = f1[gi0];
                out[2*NVOX + gi1] = f1[gi1];
            }
        } else {
            int pc = pbase + (vz+2)*PPLANE + (wy+yi+2)*PW + lane + 2;
            qnext[pc]          = make_float2(Ic[0][yi], fmaf(dB1m, res0, dB0));
            qnext[pc + PPLANE] = make_float2(Ic[1][yi], fmaf(dB1m, res1, dB0));
        }
    }
}

extern "C" void kernel_launch(void* const* d_in, const int* in_sizes, int n_in,
                              void* d_out, int out_size) {
    const float* img = (const float*)d_in[0];
    const float* h   = (const float*)d_in[1];
    const float* f1  = (const float*)d_in[2];
    const float* w0  = (const float*)d_in[3];
    const float* sw  = (const float*)d_in[4];
    const float* bw  = (const float*)d_in[5];
    const float* cm  = (const float*)d_in[6];
    float* out = (float*)d_out;

    const int SMEM_BYTES = POOLF * 4;   // 27648

    // Hard requests (host-side, graph-capture safe): allow the dynamic smem
    // size and ask for max carveout so 8 blocks (221 KB) can be resident.
    cudaFuncSetAttribute(iter_kernel<0>,
                         cudaFuncAttributeMaxDynamicSharedMemorySize, SMEM_BYTES);
    cudaFuncSetAttribute(iter_kernel<1>,
                         cudaFuncAttributeMaxDynamicSharedMemorySize, SMEM_BYTES);
    cudaFuncSetAttribute(iter_kernel<0>,
                         cudaFuncAttributePreferredSharedMemoryCarveout, 100);
    cudaFuncSetAttribute(iter_kernel<1>,
                         cudaFuncAttributePreferredSharedMemoryCarveout, 100);

    init_kernel<<<NVOX/256, 256>>>(img, h, f1, w0, sw, bw, cm);

    dim3 blk(32, 2, 4);
    dim3 grd(WW/32, HH/4, DD/8);
    int copyf1 = (out_size >= 3 * NVOX) ? 1 : 0;
    iter_kernel<0><<<grd, blk, SMEM_BYTES>>>(0, out, f1, copyf1);   // A -> B
    iter_kernel<0><<<grd, blk, SMEM_BYTES>>>(1, out, f1, copyf1);   // B -> A
    iter_kernel<0><<<grd, blk, SMEM_BYTES>>>(0, out, f1, copyf1);   // A -> B
    iter_kernel<0><<<grd, blk, SMEM_BYTES>>>(1, out, f1, copyf1);   // B -> A
    iter_kernel<1><<<grd, blk, SMEM_BYTES>>>(0, out, f1, copyf1);   // A -> out
}

// round 17
// speedup vs baseline: 1.3400x; 1.0610x over previous
#include <cuda_runtime.h>

#define DD 64
#define HH 128
#define WW 128
#define NVOX (DD*HH*WW)

// padded layout (zero borders, zero-initialized statics)
#define PH 132
#define PW 136
#define PPLANE (PH*PW)
#define PSZ (68*PPLANE)

// ---- static device state ----
// (I', s): I' = I * sqrt(2*log2(e)) pre-scaled; s = dB1m*q + dB0*m.
// padding stays (0,0) forever = mask 0.
__device__ float2 g_pA[PSZ];
__device__ float2 g_pB[PSZ];
__device__ float  g_duS2[NVOX];  // du - (dA0 - rB*dB0)*S
__device__ float  g_coef[4];     // rB, dB0, dB1m, -

// ---- blur taps (sigma=1, radius 2, normalized) ----
constexpr double c_E05 = 0.60653065971263342426;
constexpr double c_E2  = 0.13533528323661269189;
constexpr double c_KS  = 1.0 + 2.0*c_E05 + 2.0*c_E2;
#define K0F ((float)(1.0   / c_KS))
#define K1F ((float)(c_E05 / c_KS))
#define K2F ((float)(c_E2  / c_KS))

// bilateral with pre-scaled I': w = 2^(lsc - df'^2), df' = Ic' - Iv'
#define SQEXP (1.6986436f)             // sqrt(2*log2(e))
#define LSC1  (-0.3205988979944306f)
#define LSC2  (-0.6411977959888612f)
#define LSC3  (-0.9617966939832918f)

#define LOG_SQRT_2PI 0.91893853320467274178f

__device__ __forceinline__ float ex2f(float x) {
    float r; asm("ex2.approx.ftz.f32 %0, %1;" : "=f"(r) : "f"(x)); return r;
}
__device__ __forceinline__ float sigmoidf_fast(float x) {
    return __fdividef(1.0f, 1.0f + ex2f(-1.4426950408889634f * x));
}
__device__ __forceinline__ float axis_sum(int i, int N) {
    float m = 1.f;
    if (i == 0) m -= (K1F + K2F); else if (i == 1) m -= K2F;
    int j = N - 1 - i;
    if (j == 0) m -= (K1F + K2F); else if (j == 1) m -= K2F;
    return m;
}

__global__ void init_kernel(const float* __restrict__ img,
                            const float* __restrict__ h,
                            const float* __restrict__ f1,
                            const float* __restrict__ w0,
                            const float* __restrict__ sw,
                            const float* __restrict__ bw,
                            const float* __restrict__ cm) {
    int i = blockIdx.x * blockDim.x + threadIdx.x;
    if (i >= NVOX) return;
    float cm0 = cm[2] - cm[0];
    float cm1 = cm[3] - cm[1];
    float dA0  = cm0 * sw[0] + cm1 * sw[2];
    float dA1  = cm0 * sw[1] + cm1 * sw[3];
    float dB0  = cm0 * bw[0] + cm1 * bw[2];
    float dB1  = cm0 * bw[1] + cm1 * bw[3];
    float dA1m = dA1 - dA0;
    float dB1m = dB1 - dB0;
    float rB   = dA1m / dB1m;
    if (i == 0) {
        g_coef[0] = rB; g_coef[1] = dB0; g_coef[2] = dB1m;
    }
    int x = i & 127;
    int y = (i >> 7) & 127;
    int z = i >> 14;

    float I  = img[i];
    float d  = h[i + NVOX] - h[i];
    float du = d * (f1[i] - w0[0] + 0.5f*I*I + LOG_SQRT_2PI);
    float S  = axis_sum(z, DD) * axis_sum(y, HH) * axis_sum(x, WW);
    g_duS2[i] = du - (dA0 - rB * dB0) * S;

    float q = sigmoidf_fast(d);
    float s = fmaf(dB1m, q, dB0);
    int p = ((z + 2)*PH + (y + 2))*PW + (x + 4);
    g_pA[p] = make_float2(I * SQEXP, s);
}

// smem geometry (dynamic pool, 27648 B):
//   sI [12 z][8 y][36 x] f32 (3456f); later aliased by t1 [12][8][32]
//   sS [12 z][8 y][36 x] f32 (3456f); later aliased by t2 [12][4][32]
#define SROW 36
#define SPL  (8*36)     // z-plane stride
#define POOLF (2*3456)  // 6912 floats = 27648 bytes

template<int LAST>
__global__ void __launch_bounds__(256)
iter_kernel(int flip, float* __restrict__ out,
            const float* __restrict__ f1, int copyf1)
{
    extern __shared__ __align__(16) float pool[];
    float* sI = pool;            // [12][8][36]; later aliased by t1 [12][8][32]
    float* sS = pool + 3456;     // [12][8][36]; later aliased by t2 [12][4][32]
    float* t1 = pool;
    float* t2 = pool + 3456;

    const float2* __restrict__ qprev = flip ? g_pB : g_pA;
    float2*       __restrict__ qnext = flip ? g_pA : g_pB;

    const int lane = threadIdx.x;                 // 0..31 (x)
    const int ty   = threadIdx.y;                 // 0..1  (y pair)
    const int tz   = threadIdx.z;                 // 0..3  (z pair)
    const int tid  = lane + 32*(ty + 2*tz);
    const int wid  = ty + 2*tz;                   // warp 0..7
    const int x0 = blockIdx.x << 5;
    const int y0 = blockIdx.y << 2;
    const int z0 = blockIdx.z << 3;
    const int wy = ty << 1;                       // tile y base of pair
    const int vz = tz << 1;                       // tile z base of pair

    // padded index of (z0-2, y0-2, x0-2)
    const int pbase = (z0*PH + y0)*PW + x0 + 2;

    // ---- prefetch per-voxel unary + coefs (latency hidden by halo/bilateral) ----
    const int gzb = z0 + vz;
    const int gib = (gzb*HH + (y0 + wy))*WW + x0 + lane;
    float du00 = g_duS2[gib];
    float du01 = g_duS2[gib + WW];
    float du10 = g_duS2[gib + HH*WW];
    float du11 = g_duS2[gib + HH*WW + WW];
    const float rB   = g_coef[0];
    const float dB0  = g_coef[1];
    const float dB1m = g_coef[2];

    // ---- halo load: 96 rows (12z x 8y) x 36, split into scalar planes ----
    #pragma unroll
    for (int k = 0; k < 12; k++) {
        int r  = wid + (k << 3);      // 0..95
        int lz = r >> 3;
        int ly = r & 7;
        int a  = pbase + lz*PPLANE + ly*PW + lane;
        int si = lz*SPL + ly*SROW + lane;
        float2 v = qprev[a];
        sI[si] = v.x;
        sS[si] = v.y;
        if (lane < 4) {
            float2 v2 = qprev[a + 32];
            sI[si + 32] = v2.x;
            sS[si + 32] = v2.y;
        }
    }
    __syncthreads();

    // ---- bilateral 2x2 quad: 48 shared positions serve 104 taps ----
    // Internal center-center taps (6 symmetric pairs) computed once, shared.
    float Ic[2][2], sc[2][2], den[2][2], acc[2][2], pb[2][2];
    #pragma unroll
    for (int zi = 0; zi < 2; zi++)
        #pragma unroll
        for (int yi = 0; yi < 2; yi++) {
            int c = (vz+2+zi)*SPL + (wy+2+yi)*SROW + lane + 2;
            Ic[zi][yi]  = sI[c];
            sc[zi][yi]  = sS[c];
            acc[zi][yi] = sc[zi][yi];   // center weight = 1 exactly
            den[zi][yi] = 1.f;
        }

    // 6 symmetric internal pairs (z-edges, y-edges, 2 diagonals)
    {
        #define PAIRW(z0i,y0i,z1i,y1i,LSCV) {                                   \
            float df = Ic[z0i][y0i] - Ic[z1i][y1i];                             \
            float w  = ex2f(fmaf(df, -df, LSCV));                               \
            den[z0i][y0i] += w;                                                 \
            acc[z0i][y0i] = fmaf(w, sc[z1i][y1i], acc[z0i][y0i]);               \
            den[z1i][y1i] += w;                                                 \
            acc[z1i][y1i] = fmaf(w, sc[z0i][y0i], acc[z1i][y1i]);               \
        }
        PAIRW(0,0, 1,0, LSC1)
        PAIRW(0,1, 1,1, LSC1)
        PAIRW(0,0, 0,1, LSC1)
        PAIRW(1,0, 1,1, LSC1)
        PAIRW(0,0, 1,1, LSC2)
        PAIRW(1,0, 0,1, LSC2)
        #undef PAIRW
    }

    #pragma unroll
    for (int pp = 0; pp < 4; pp++) {
        #pragma unroll
        for (int rr = 0; rr < 4; rr++) {
            #pragma unroll
            for (int cc = 0; cc < 3; cc++) {
                // position is a quad center iff pp,rr in {1,2} and cc==1
                const bool is_center_pos =
                    (cc == 1) && (pp == 1 || pp == 2) && (rr == 1 || rr == 2);
                const int idx = (vz+1+pp)*SPL + (wy+1+rr)*SROW + lane + 1 + cc;
                float Iv = sI[idx];
                float Sv = sS[idx];
                #pragma unroll
                for (int zi = 0; zi < 2; zi++) {
                    const int dz = pp - 1 - zi;
                    if (dz < -1 || dz > 1) continue;
                    #pragma unroll
                    for (int yi = 0; yi < 2; yi++) {
                        const int dy = rr - 1 - yi;
                        if (dy < -1 || dy > 1) continue;
                        const int d2 = dz*dz + dy*dy + (cc-1)*(cc-1);
                        if (d2 == 0) continue;
                        if (is_center_pos) continue;   // handled by PAIRW above
                        const float lsc = (d2 == 1) ? LSC1 : (d2 == 2) ? LSC2 : LSC3;
                        float df = Ic[zi][yi] - Iv;
                        float w  = ex2f(fmaf(df, -df, lsc));
                        den[zi][yi] += w;
                        acc[zi][yi] = fmaf(w, Sv, acc[zi][yi]);
                    }
                }
            }
        }
    }
    #pragma unroll
    for (int zi = 0; zi < 2; zi++)
        #pragma unroll
        for (int yi = 0; yi < 2; yi++)
            pb[zi][yi] = __fdividef(acc[zi][yi], den[zi][yi]);
    __syncthreads();   // all sI reads done; t1 may overwrite

    // ---- x-blur on sS -> t1 [12][8][32]: 768 quads, 3 per thread ----
    #pragma unroll
    for (int k = 0; k < 3; k++) {
        int e   = tid + (k << 8);
        int row = e >> 3;             // 0..95
        int qx  = e & 7;
        const float* rp = sS + row*SROW + (qx << 2);
        float4 a = *(const float4*)rp;        // s[j .. j+3]
        float4 b = *(const float4*)(rp + 4);  // s[j+4 .. j+7]
        float4 o;
        o.x = K2F*(a.x + b.x) + K1F*(a.y + a.w) + K0F*a.z;
        o.y = K2F*(a.y + b.y) + K1F*(a.z + b.x) + K0F*a.w;
        o.z = K2F*(a.z + b.z) + K1F*(a.w + b.y) + K0F*b.x;
        o.w = K2F*(a.w + b.w) + K1F*(b.x + b.z) + K0F*b.y;
        *(float4*)(t1 + row*32 + (qx << 2)) = o;
    }
    __syncthreads();   // all sS reads done; t2 may overwrite

    // ---- y-blur t1 -> t2 [12][4][32]: 384 quads (256 + 128) ----
    {
        int r2 = tid >> 3;            // 0..31
        int q2 = tid & 7;
        int lz = r2 >> 2;
        int yy = r2 & 3;
        const float* bp = t1 + (lz*8 + yy)*32 + (q2 << 2);
        float4 r0 = *(const float4*)(bp);
        float4 r1 = *(const float4*)(bp + 32);
        float4 r2v = *(const float4*)(bp + 64);
        float4 r3 = *(const float4*)(bp + 96);
        float4 r4 = *(const float4*)(bp + 128);
        float4 o;
        o.x = K2F*(r0.x+r4.x) + K1F*(r1.x+r3.x) + K0F*r2v.x;
        o.y = K2F*(r0.y+r4.y) + K1F*(r1.y+r3.y) + K0F*r2v.y;
        o.z = K2F*(r0.z+r4.z) + K1F*(r1.z+r3.z) + K0F*r2v.z;
        o.w = K2F*(r0.w+r4.w) + K1F*(r1.w+r3.w) + K0F*r2v.w;
        *(float4*)(t2 + (lz*4 + yy)*32 + (q2 << 2)) = o;
    }
    if (tid < 128) {
        int e2 = tid + 256;
        int r2 = e2 >> 3;             // 32..47
        int q2 = e2 & 7;
        int lz = r2 >> 2;
        int yy = r2 & 3;
        const float* bp = t1 + (lz*8 + yy)*32 + (q2 << 2);
        float4 r0 = *(const float4*)(bp);
        float4 r1 = *(const float4*)(bp + 32);
        float4 r2v = *(const float4*)(bp + 64);
        float4 r3 = *(const float4*)(bp + 96);
        float4 r4 = *(const float4*)(bp + 128);
        float4 o;
        o.x = K2F*(r0.x+r4.x) + K1F*(r1.x+r3.x) + K0F*r2v.x;
        o.y = K2F*(r0.y+r4.y) + K1F*(r1.y+r3.y) + K0F*r2v.y;
        o.z = K2F*(r0.z+r4.z) + K1F*(r1.z+r3.z) + K0F*r2v.z;
        o.w = K2F*(r0.w+r4.w) + K1F*(r1.w+r3.w) + K0F*r2v.w;
        *(float4*)(t2 + (lz*4 + yy)*32 + (q2 << 2)) = o;
    }
    __syncthreads();

    // ---- z-blur + combine + write (4 voxels) ----
    #pragma unroll
    for (int yi = 0; yi < 2; yi++) {
        float c0 = t2[((vz+0)*4 + wy+yi)*32 + lane];
        float c1 = t2[((vz+1)*4 + wy+yi)*32 + lane];
        float c2 = t2[((vz+2)*4 + wy+yi)*32 + lane];
        float c3 = t2[((vz+3)*4 + wy+yi)*32 + lane];
        float c4 = t2[((vz+4)*4 + wy+yi)*32 + lane];
        float c5 = t2[((vz+5)*4 + wy+yi)*32 + lane];
        float sp0 = K2F*(c0+c4) + K1F*(c1+c3) + K0F*c2;
        float sp1 = K2F*(c1+c5) + K1F*(c2+c4) + K0F*c3;

        const int gi0 = gib + yi*WW;
        const int gi1 = gi0 + HH*WW;
        float duv0 = yi ? du01 : du00;
        float duv1 = yi ? du11 : du10;

        float d0 = duv0 - rB*sp0 - pb[0][yi];
        float d1 = duv1 - rB*sp1 - pb[1][yi];
        float res0 = sigmoidf_fast(d0);
        float res1 = sigmoidf_fast(d1);

        if (LAST) {
            out[gi0]        = 1.f - res0;
            out[NVOX + gi0] = res0;
            out[gi1]        = 1.f - res1;
            out[NVOX + gi1] = res1;
            if (copyf1) {
                out[2*NVOX + gi0] = f1[gi0];
                out[2*NVOX + gi1] = f1[gi1];
            }
        } else {
            int pc = pbase + (vz+2)*PPLANE + (wy+yi+2)*PW + lane + 2;
            qnext[pc]          = make_float2(Ic[0][yi], fmaf(dB1m, res0, dB0));
            qnext[pc + PPLANE] = make_float2(Ic[1][yi], fmaf(dB1m, res1, dB0));
        }
    }
}

extern "C" void kernel_launch(void* const* d_in, const int* in_sizes, int n_in,
                              void* d_out, int out_size) {
    const float* img = (const float*)d_in[0];
    const float* h   = (const float*)d_in[1];
    const float* f1  = (const float*)d_in[2];
    const float* w0  = (const float*)d_in[3];
    const float* sw  = (const float*)d_in[4];
    const float* bw  = (const float*)d_in[5];
    const float* cm  = (const float*)d_in[6];
    float* out = (float*)d_out;

    const int SMEM_BYTES = POOLF * 4;   // 27648

    cudaFuncSetAttribute(iter_kernel<0>,
                         cudaFuncAttributeMaxDynamicSharedMemorySize, SMEM_BYTES);
    cudaFuncSetAttribute(iter_kernel<1>,
                         cudaFuncAttributeMaxDynamicSharedMemorySize, SMEM_BYTES);
    cudaFuncSetAttribute(iter_kernel<0>,
                         cudaFuncAttributePreferredSharedMemoryCarveout, 100);
    cudaFuncSetAttribute(iter_kernel<1>,
                         cudaFuncAttributePreferredSharedMemoryCarveout, 100);

    init_kernel<<<NVOX/256, 256>>>(img, h, f1, w0, sw, bw, cm);

    dim3 blk(32, 2, 4);
    dim3 grd(WW/32, HH/4, DD/8);
    int copyf1 = (out_size >= 3 * NVOX) ? 1 : 0;
    iter_kernel<0><<<grd, blk, SMEM_BYTES>>>(0, out, f1, copyf1);   // A -> B
    iter_kernel<0><<<grd, blk, SMEM_BYTES>>>(1, out, f1, copyf1);   // B -> A
    iter_kernel<0><<<grd, blk, SMEM_BYTES>>>(0, out, f1, copyf1);   // A -> B
    iter_kernel<0><<<grd, blk, SMEM_BYTES>>>(1, out, f1, copyf1);   // B -> A
    iter_kernel<1><<<grd, blk, SMEM_BYTES>>>(0, out, f1, copyf1);   // A -> out
}